// round 2
// baseline (speedup 1.0000x reference)
#include <cuda_runtime.h>

#define NXg 4096
#define NYg 4096
// vec4 lanes per row
#define JV  (NYg / 4)   // 1024

__global__ __launch_bounds__(256)
void diffreact_step(const float* __restrict__ state,
                    const float* __restrict__ bc,
                    const float* __restrict__ a_p,
                    const float* __restrict__ b_p,
                    const float* __restrict__ k_p,
                    float* __restrict__ out)
{
    const int v  = blockIdx.x * 256 + threadIdx.x;   // one float4 of one row, both channels
    const int i  = v >> 10;        // row (JV = 1024 = 2^10)
    const int jv = v & (JV - 1);   // vec4 index within the row
    const long base = (long)i * NYg + ((long)jv << 2);

    const long plane = (long)NXg * NYg;
    const float* __restrict__ U = state;
    const float* __restrict__ V = state + plane;
    float* __restrict__ outU = out;
    float* __restrict__ outV = out + plane;

    // parameters: a,b,k = sigmoid(x)*0.01 ; fold inv_dx2=100 into diffusion coeffs
    const float a  = 0.01f / (1.0f + __expf(-__ldg(a_p)));
    const float b  = 0.01f / (1.0f + __expf(-__ldg(b_p)));
    const float k  = 0.01f / (1.0f + __expf(-__ldg(k_p)));
    const float ai = a * 100.0f;   // a * inv_dx2
    const float bi = b * 100.0f;   // b * inv_dx2

    // bc layout: [0,0,:] = U {left,right,top,bottom}; [0,1,:] = V {left,right,top,bottom}
    // center tiles
    const float4 uc = *reinterpret_cast<const float4*>(U + base);
    const float4 vc = *reinterpret_cast<const float4*>(V + base);

    // up / down rows (top bc at i==0, bottom bc at i==NX-1)
    float4 uu, ud, vu, vd;
    if (i > 0) {
        uu = *reinterpret_cast<const float4*>(U + base - NYg);
        vu = *reinterpret_cast<const float4*>(V + base - NYg);
    } else {
        const float tU = __ldg(bc + 2), tV = __ldg(bc + 6);
        uu = make_float4(tU, tU, tU, tU);
        vu = make_float4(tV, tV, tV, tV);
    }
    if (i < NXg - 1) {
        ud = *reinterpret_cast<const float4*>(U + base + NYg);
        vd = *reinterpret_cast<const float4*>(V + base + NYg);
    } else {
        const float bU = __ldg(bc + 3), bV = __ldg(bc + 7);
        ud = make_float4(bU, bU, bU, bU);
        vd = make_float4(bV, bV, bV, bV);
    }

    // left / right halo scalars (left bc at jv==0, right bc at jv==JV-1)
    const float ul = (jv > 0)      ? __ldg(U + base - 1) : __ldg(bc + 0);
    const float ur = (jv < JV - 1) ? __ldg(U + base + 4) : __ldg(bc + 1);
    const float vl = (jv > 0)      ? __ldg(V + base - 1) : __ldg(bc + 4);
    const float vr = (jv < JV - 1) ? __ldg(V + base + 4) : __ldg(bc + 5);

    // 5-point laplacian sums (inv_dx2 folded into ai/bi)
    float4 lu, lv;
    lu.x = uu.x + ud.x + ul   + uc.y - 4.0f * uc.x;
    lu.y = uu.y + ud.y + uc.x + uc.z - 4.0f * uc.y;
    lu.z = uu.z + ud.z + uc.y + uc.w - 4.0f * uc.z;
    lu.w = uu.w + ud.w + uc.z + ur   - 4.0f * uc.w;

    lv.x = vu.x + vd.x + vl   + vc.y - 4.0f * vc.x;
    lv.y = vu.y + vd.y + vc.x + vc.z - 4.0f * vc.y;
    lv.z = vu.z + vd.z + vc.y + vc.w - 4.0f * vc.z;
    lv.w = vu.w + vd.w + vc.z + vr   - 4.0f * vc.w;

    // reaction terms:
    //   dU = a*lapU + U - U^3 - V - k
    //   dV = b*lapV + U - V
    float4 dU, dV;
    dU.x = fmaf(ai, lu.x, uc.x - uc.x * uc.x * uc.x - vc.x - k);
    dU.y = fmaf(ai, lu.y, uc.y - uc.y * uc.y * uc.y - vc.y - k);
    dU.z = fmaf(ai, lu.z, uc.z - uc.z * uc.z * uc.z - vc.z - k);
    dU.w = fmaf(ai, lu.w, uc.w - uc.w * uc.w * uc.w - vc.w - k);

    dV.x = fmaf(bi, lv.x, uc.x - vc.x);
    dV.y = fmaf(bi, lv.y, uc.y - vc.y);
    dV.z = fmaf(bi, lv.z, uc.z - vc.z);
    dV.w = fmaf(bi, lv.w, uc.w - vc.w);

    *reinterpret_cast<float4*>(outU + base) = dU;
    *reinterpret_cast<float4*>(outV + base) = dV;
}

extern "C" void kernel_launch(void* const* d_in, const int* in_sizes, int n_in,
                              void* d_out, int out_size)
{
    const float* state = (const float*)d_in[0];  // (1,2,4096,4096) f32
    const float* bc    = (const float*)d_in[1];  // (1,2,4) f32
    const float* a_p   = (const float*)d_in[2];
    const float* b_p   = (const float*)d_in[3];
    const float* k_p   = (const float*)d_in[4];
    float* out = (float*)d_out;

    const int total_vec = NXg * JV;              // 4,194,304 float4-threads
    const int threads = 256;
    const int blocks = total_vec / threads;      // 16384
    diffreact_step<<<blocks, threads>>>(state, bc, a_p, b_p, k_p, out);
}

// round 3
// speedup vs baseline: 1.3276x; 1.3276x over previous
#include <cuda_runtime.h>

#define NXg 4096
#define NYg 4096
#define JV  (NYg / 4)   // 1024 float4 lanes per row
#define RSTRIP 8        // rows swept per thread

__global__ __launch_bounds__(256)
void diffreact_sweep(const float* __restrict__ state,
                     const float* __restrict__ bc,
                     const float* __restrict__ a_p,
                     const float* __restrict__ b_p,
                     const float* __restrict__ k_p,
                     float* __restrict__ out)
{
    const int tid   = blockIdx.x * 256 + threadIdx.x;
    const int strip = tid >> 10;          // JV = 1024 = 2^10
    const int jv    = tid & (JV - 1);
    const int lane  = threadIdx.x & 31;   // warps are row-aligned (1024 % 32 == 0)
    const int i0    = strip * RSTRIP;

    const long plane = (long)NXg * NYg;
    const float* __restrict__ U = state;
    const float* __restrict__ V = state + plane;
    float* __restrict__ outU = out;
    float* __restrict__ outV = out + plane;

    // params: a,b,k = sigmoid(x)*0.01 ; fold inv_dx2 = 100 into diffusion coeff
    const float a  = 0.01f / (1.0f + __expf(-__ldg(a_p)));
    const float b  = 0.01f / (1.0f + __expf(-__ldg(b_p)));
    const float k  = 0.01f / (1.0f + __expf(-__ldg(k_p)));
    const float ai = a * 100.0f;
    const float bi = b * 100.0f;

    // bc: [0,0,:]=U {l,r,t,b}; [0,1,:]=V {l,r,t,b}
    const float blU = __ldg(bc + 0), brU = __ldg(bc + 1), btU = __ldg(bc + 2), bbU = __ldg(bc + 3);
    const float blV = __ldg(bc + 4), brV = __ldg(bc + 5), btV = __ldg(bc + 6), bbV = __ldg(bc + 7);

    long base = (long)i0 * NYg + ((long)jv << 2);

    // prime: up-row and current row
    float4 up_u, up_v;
    if (i0 > 0) {
        up_u = *reinterpret_cast<const float4*>(U + base - NYg);
        up_v = *reinterpret_cast<const float4*>(V + base - NYg);
    } else {
        up_u = make_float4(btU, btU, btU, btU);
        up_v = make_float4(btV, btV, btV, btV);
    }
    float4 cu = *reinterpret_cast<const float4*>(U + base);
    float4 cv = *reinterpret_cast<const float4*>(V + base);

#pragma unroll
    for (int r = 0; r < RSTRIP; ++r) {
        const int i = i0 + r;

        // next (down) row — only vector loads in the steady state
        float4 dn_u, dn_v;
        if (i < NXg - 1) {
            dn_u = *reinterpret_cast<const float4*>(U + base + NYg);
            dn_v = *reinterpret_cast<const float4*>(V + base + NYg);
        } else {
            dn_u = make_float4(bbU, bbU, bbU, bbU);
            dn_v = make_float4(bbV, bbV, bbV, bbV);
        }

        // horizontal halos via warp shuffle; lanes 0/31 patch from gmem / bc
        float ul = __shfl_up_sync(0xffffffffu, cu.w, 1);
        float vl = __shfl_up_sync(0xffffffffu, cv.w, 1);
        float ur = __shfl_down_sync(0xffffffffu, cu.x, 1);
        float vr = __shfl_down_sync(0xffffffffu, cv.x, 1);
        if (lane == 0) {
            ul = (jv > 0) ? __ldg(U + base - 1) : blU;
            vl = (jv > 0) ? __ldg(V + base - 1) : blV;
        }
        if (lane == 31) {
            ur = (jv < JV - 1) ? __ldg(U + base + 4) : brU;
            vr = (jv < JV - 1) ? __ldg(V + base + 4) : brV;
        }

        // 5-point laplacian sums (inv_dx2 folded into ai/bi)
        float4 lu, lv;
        lu.x = up_u.x + dn_u.x + ul   + cu.y - 4.0f * cu.x;
        lu.y = up_u.y + dn_u.y + cu.x + cu.z - 4.0f * cu.y;
        lu.z = up_u.z + dn_u.z + cu.y + cu.w - 4.0f * cu.z;
        lu.w = up_u.w + dn_u.w + cu.z + ur   - 4.0f * cu.w;

        lv.x = up_v.x + dn_v.x + vl   + cv.y - 4.0f * cv.x;
        lv.y = up_v.y + dn_v.y + cv.x + cv.z - 4.0f * cv.y;
        lv.z = up_v.z + dn_v.z + cv.y + cv.w - 4.0f * cv.z;
        lv.w = up_v.w + dn_v.w + cv.z + vr   - 4.0f * cv.w;

        // dU = a*lapU + U - U^3 - V - k ; dV = b*lapV + U - V
        float4 dU, dV;
        dU.x = fmaf(ai, lu.x, cu.x - cu.x * cu.x * cu.x - cv.x - k);
        dU.y = fmaf(ai, lu.y, cu.y - cu.y * cu.y * cu.y - cv.y - k);
        dU.z = fmaf(ai, lu.z, cu.z - cu.z * cu.z * cu.z - cv.z - k);
        dU.w = fmaf(ai, lu.w, cu.w - cu.w * cu.w * cu.w - cv.w - k);

        dV.x = fmaf(bi, lv.x, cu.x - cv.x);
        dV.y = fmaf(bi, lv.y, cu.y - cv.y);
        dV.z = fmaf(bi, lv.z, cu.z - cv.z);
        dV.w = fmaf(bi, lv.w, cu.w - cv.w);

        *reinterpret_cast<float4*>(outU + base) = dU;
        *reinterpret_cast<float4*>(outV + base) = dV;

        // rotate the row window
        up_u = cu; up_v = cv;
        cu = dn_u; cv = dn_v;
        base += NYg;
    }
}

extern "C" void kernel_launch(void* const* d_in, const int* in_sizes, int n_in,
                              void* d_out, int out_size)
{
    const float* state = (const float*)d_in[0];  // (1,2,4096,4096) f32
    const float* bc    = (const float*)d_in[1];  // (1,2,4) f32
    const float* a_p   = (const float*)d_in[2];
    const float* b_p   = (const float*)d_in[3];
    const float* k_p   = (const float*)d_in[4];
    float* out = (float*)d_out;

    const int total_threads = (NXg / RSTRIP) * JV;  // 512 * 1024 = 524288
    const int threads = 256;
    const int blocks  = total_threads / threads;    // 2048
    diffreact_sweep<<<blocks, threads>>>(state, bc, a_p, b_p, k_p, out);
}